// round 12
// baseline (speedup 1.0000x reference)
#include <cuda_runtime.h>
#include <cuda_bf16.h>
#include <cstdint>

// ---------------------------------------------------------------------------
// Dcls1d via mma.sync (HMMA) bf16 split-GEMM, ACTIVE-d COMPACTION.
//   out[b,o,t] = bias[o] + sum_{d,i} K2[d,o,i] * x[b,i,t+d-16]
//   fp32 = bf16 hi+lo, products hh+hl+lh, fp32 accum.
// R12: K2 stored in m16n8k16 A-FRAGMENT order -> A loaded per-warp with
//      direct LDG.128 (no smem / ldmatrix / barriers for A). X double-
//      buffered in smem; staging fully overlapped. d-loop is sync-free.
// ---------------------------------------------------------------------------

#define B_   8
#define C_   256
#define T_   2048
#define O_   256
#define DKS_ 33
#define KC_  16
#define TP_  2080   // 16 + 2048 + 16 padded time rows
#define KSZ  (DKS_ * O_ * C_)      // elements per tensor (2,162,688)

__device__ __nv_bfloat16 g_Kf[2 * KSZ];           // fragment-ordered K2 (hi, lo)
__device__ __nv_bfloat16 g_Xhi[B_ * TP_ * C_];    // [b][t+16][i]
__device__ __nv_bfloat16 g_Xlo[B_ * TP_ * C_];
__device__ unsigned long long g_maskblk[O_];      // per-o nonzero-slice mask

// ---- PTX helpers -----------------------------------------------------------
__device__ __forceinline__ uint32_t smem_u32(const void* p) {
    uint32_t a;
    asm("{ .reg .u64 t; cvta.to.shared.u64 t, %1; cvt.u32.u64 %0, t; }"
        : "=r"(a) : "l"(p));
    return a;
}
__device__ __forceinline__ void cpa16(uint32_t dst, const void* src) {
    asm volatile("cp.async.ca.shared.global [%0], [%1], 16;" :: "r"(dst), "l"(src));
}
#define CP_COMMIT() asm volatile("cp.async.commit_group;" ::: "memory")
#define CP_WAIT0()  asm volatile("cp.async.wait_group 0;" ::: "memory")

__device__ __forceinline__ void ldmx4(uint32_t* r, uint32_t addr) {
    asm volatile("ldmatrix.sync.aligned.m8n8.x4.shared.b16 {%0,%1,%2,%3}, [%4];"
                 : "=r"(r[0]), "=r"(r[1]), "=r"(r[2]), "=r"(r[3]) : "r"(addr));
}
// MMA with A given as uint4 (fragment regs a0..a3 = .x...w)
#define MMAU4(dv, av, b0v, b1v)                                                \
    asm volatile("mma.sync.aligned.m16n8k16.row.col.f32.bf16.bf16.f32 "        \
                 "{%0,%1,%2,%3},{%4,%5,%6,%7},{%8,%9},{%0,%1,%2,%3};"          \
                 : "+f"((dv)[0]), "+f"((dv)[1]), "+f"((dv)[2]), "+f"((dv)[3])  \
                 : "r"((av).x), "r"((av).y), "r"((av).z), "r"((av).w),         \
                   "r"(b0v), "r"(b1v))

// ---------------------------------------------------------------------------
// Fused prep: blocks [0,4096) x transpose/split+pads; [4096,4352) build K2
// into fragment-ordered layout.
// ---------------------------------------------------------------------------
__global__ void prep(const float* __restrict__ x,
                     const float* __restrict__ w,
                     const float* __restrict__ P) {
    __shared__ float sm[32][33];
    __shared__ unsigned long long s_m[8];
    const int tid = threadIdx.x;

    if (blockIdx.x < 4096) {
        int blk = blockIdx.x;
        int t0 = (blk & 63) * 32;
        int i0 = ((blk >> 6) & 7) * 32;
        int b  = blk >> 9;
        int tl = tid & 31, th = tid >> 5;

        if ((blk & 63) == 0) {   // zero pads
#pragma unroll
            for (int k = 0; k < 2; ++k) {
                int e = tid + k * 256;
                int r = e >> 5, cc = e & 31;
                size_t o1 = ((size_t)b * TP_ + r) * C_ + i0 + cc;
                size_t o2 = ((size_t)b * TP_ + (TP_ - 16 + r)) * C_ + i0 + cc;
                g_Xhi[o1] = __float2bfloat16(0.f);
                g_Xlo[o1] = __float2bfloat16(0.f);
                g_Xhi[o2] = __float2bfloat16(0.f);
                g_Xlo[o2] = __float2bfloat16(0.f);
            }
        }
#pragma unroll
        for (int k = 0; k < 4; ++k) {
            int i = i0 + th + k * 8;
            sm[th + k * 8][tl] = x[((size_t)b * C_ + i) * T_ + t0 + tl];
        }
        __syncthreads();
#pragma unroll
        for (int k = 0; k < 4; ++k) {
            int t = t0 + th + k * 8;
            float v = sm[tl][th + k * 8];
            __nv_bfloat16 h = __float2bfloat16(v);
            __nv_bfloat16 l = __float2bfloat16(v - __bfloat162float(h));
            size_t idx = ((size_t)b * TP_ + t + 16) * C_ + i0 + tl;
            g_Xhi[idx] = h;
            g_Xlo[idx] = l;
        }
    } else {
        // ---- build_k2 (gather form) -> fragment-ordered store ----
        int bk = blockIdx.x - 4096;               // out-channel o
        int oi = bk * 256 + tid;                  // tid = input channel i
        const float* Prow  = P + (size_t)oi * KC_;
        const float* P0row = P + (size_t)tid * KC_;  // out-channel 0 (frac src)
        const float* Wrow  = w + (size_t)oi * KC_;

        int   pi[KC_];
        float c1[KC_], c2[KC_];
#pragma unroll
        for (int k = 0; k < KC_; ++k) {
            float pp  = Prow[k] + 16.f;
            pi[k]     = (int)floorf(pp);
            float pp0 = P0row[k] + 16.f;
            float fr  = pp0 - floorf(pp0);
            float wv  = Wrow[k];
            c1[k] = wv * (1.f - fr);
            c2[k] = wv * fr;
        }
        // fragment coordinates (PTX m16n8k16 A layout)
        const int row  = bk & 15,  o16 = bk >> 4;
        const int col  = tid & 15, i16 = tid >> 4;
        const int lane = (row & 7) * 4 + ((col & 7) >> 1);
        const int reg  = (row >> 3) + ((col >> 3) << 1);
        const int sub  = reg * 2 + (col & 1);     // bf16 slot within 8-elem group

        unsigned long long bits = 0ull;
#pragma unroll
        for (int d = 0; d < DKS_; ++d) {
            float v = 0.f;
#pragma unroll
            for (int k = 0; k < KC_; ++k) {
                if (pi[k] == d)     v += c1[k];
                if (pi[k] + 1 == d) v += c2[k];
            }
            if (v != 0.f) bits |= 1ull << d;
            __nv_bfloat16 h = __float2bfloat16(v);
            __nv_bfloat16 l = __float2bfloat16(v - __bfloat162float(h));
            size_t e = ((size_t)(((d * 16 + o16) * 16 + i16) * 32 + lane) << 3) + sub;
            g_Kf[e]       = h;
            g_Kf[KSZ + e] = l;
        }
#pragma unroll
        for (int s = 16; s > 0; s >>= 1)
            bits |= __shfl_xor_sync(0xffffffffu, bits, s);
        if ((tid & 31) == 0) s_m[tid >> 5] = bits;
        __syncthreads();
        if (tid == 0) {
            unsigned long long m = 0ull;
#pragma unroll
            for (int q = 0; q < 8; ++q) m |= s_m[q];
            g_maskblk[bk] = m;
        }
    }
}

// ---------------------------------------------------------------------------
// GEMM kernel.
// Block: 128 o x 256 t, 512 threads (16 warps: 4Mx4N, warp = 32 o x 64 t).
// ic-chunk = 64 i (4 chunks). A: direct LDG.128 fragments (1 kk prefetch).
// X: double-buffered smem (144B rows, conflict-free LDSM), staging hidden.
// ---------------------------------------------------------------------------
#define ROWB   144u
#define X_TS   41472u              // one X tensor (288*144)
#define XBUF   82944u              // hi+lo pair
#define DSMEM  (2u * XBUF + 128u)  // 166016

__global__ __launch_bounds__(512, 1)
void conv_mma(const float* __restrict__ bias, float* __restrict__ out) {
    extern __shared__ char dsm_raw[];
    uint32_t raw  = smem_u32(dsm_raw);
    uint32_t base = (raw + 127u) & ~127u;

    __shared__ unsigned long long s_part[4];
    __shared__ int s_act[DKS_];
    __shared__ int s_n;

    const int tid  = threadIdx.x;
    const int lane = tid & 31, w = tid >> 5;
    const int wm = w & 3, wn = w >> 2;            // 4 M-warps x 4 N-warps
    const int b  = blockIdx.x >> 3;
    const int t0 = (blockIdx.x & 7) * 256;
    const int o0 = blockIdx.y * 128;

    // ---- prologue: OR-reduce per-o masks -> active-d list ----
    if (tid < 128) {
        unsigned long long m = g_maskblk[o0 + tid];
#pragma unroll
        for (int s = 16; s > 0; s >>= 1)
            m |= __shfl_xor_sync(0xffffffffu, m, s);
        if (lane == 0) s_part[w] = m;
    }
    __syncthreads();
    if (tid == 0) {
        unsigned long long m = s_part[0] | s_part[1] | s_part[2] | s_part[3];
        int n = 0;
        for (int d = 0; d < DKS_; ++d)
            if (m & (1ull << d)) s_act[n++] = d;
        s_n = n;
    }
    __syncthreads();
    const int n_act = s_n;

    const uint32_t X0 = base;

    float acc[2][8][4];
#pragma unroll
    for (int mi = 0; mi < 2; ++mi)
#pragma unroll
        for (int nf = 0; nf < 8; ++nf)
#pragma unroll
            for (int q = 0; q < 4; ++q) acc[mi][nf][q] = 0.f;

    // B ldmatrix per-lane offsets
    const uint32_t b_r = (lane & 7) + 8 * (lane >> 4);
    const uint32_t b_c = (uint32_t)((lane >> 3) & 1) * 16;

    // A fragment base indices (uint4 units)
    const uint4* __restrict__ Kf4 = (const uint4*)g_Kf;
    const uint32_t KLO4 = (uint32_t)(KSZ / 8);
    const int o16a = (o0 >> 4) + wm * 2;          // mi = 0
    const int o16b = o16a + 1;                    // mi = 1

    if (n_act > 0) {
        // stage X(ic=0)
#pragma unroll
        for (int k = 0; k < 9; ++k) {
            int idx = tid + k * 512;
            int tn  = idx >= 2304;
            int r   = (idx - tn * 2304) >> 3;
            int c   = idx & 7;
            const __nv_bfloat16* src = (tn ? g_Xlo : g_Xhi)
                + ((size_t)(b * TP_ + t0 + r) * 256 + c * 8);
            cpa16(X0 + (uint32_t)tn * X_TS + r * ROWB + c * 16, src);
        }
        CP_COMMIT();

        // A prefetch state
        uint4 Af[2][4];
        int ni_ic = 0, ni_j = 0, ni_kk = 0;
        auto loadA = [&](int bufi) {
            if (ni_ic < 4) {
                int dd  = s_act[ni_j];
                int i16 = ni_ic * 4 + ni_kk;
                uint32_t e0 = (uint32_t)(((dd * 16 + o16a) * 16 + i16) * 32 + lane);
                uint32_t e1 = (uint32_t)(((dd * 16 + o16b) * 16 + i16) * 32 + lane);
                Af[bufi][0] = Kf4[e0];            // hi, mi=0
                Af[bufi][1] = Kf4[e1];            // hi, mi=1
                Af[bufi][2] = Kf4[KLO4 + e0];     // lo, mi=0
                Af[bufi][3] = Kf4[KLO4 + e1];     // lo, mi=1
            }
            if (++ni_kk == 4) { ni_kk = 0; if (++ni_j == n_act) { ni_j = 0; ++ni_ic; } }
        };
        loadA(0);                                  // (ic0, j0, kk0) -> buf0

        CP_WAIT0();
        __syncthreads();                           // X(0) visible

        for (int ic = 0; ic < 4; ++ic) {
            const uint32_t Xb = X0 + (uint32_t)(ic & 1) * XBUF;
            // start staging X(ic+1) into the other buffer (hidden by compute)
            if (ic < 3) {
#pragma unroll
                for (int k = 0; k < 9; ++k) {
                    int idx = tid + k * 512;
                    int tn  = idx >= 2304;
                    int r   = (idx - tn * 2304) >> 3;
                    int c   = idx & 7;
                    const __nv_bfloat16* src = (tn ? g_Xlo : g_Xhi)
                        + ((size_t)(b * TP_ + t0 + r) * 256 + (ic + 1) * 64 + c * 8);
                    cpa16(X0 + (uint32_t)((ic + 1) & 1) * XBUF
                          + (uint32_t)tn * X_TS + r * ROWB + c * 16, src);
                }
                CP_COMMIT();
            }

            // ---- sync-free compute over active d, kk ----
#pragma unroll 1
            for (int j = 0; j < n_act; ++j) {
                const int d = s_act[j];
#pragma unroll
                for (int kk = 0; kk < 4; ++kk) {
                    loadA((kk + 1) & 1);           // prefetch next (j,kk)
                    const uint4 AH0 = Af[kk & 1][0], AH1 = Af[kk & 1][1];
                    const uint4 AL0 = Af[kk & 1][2], AL1 = Af[kk & 1][3];
#pragma unroll
                    for (int p = 0; p < 4; ++p) {
                        uint32_t bh[4], bl[4];
                        uint32_t bd = Xb + (wn * 64 + d + p * 16 + b_r) * ROWB
                                    + kk * 32 + b_c;
                        ldmx4(bh, bd);
                        ldmx4(bl, bd + X_TS);
#pragma unroll
                        for (int nn = 0; nn < 2; ++nn) {
                            MMAU4(acc[0][p * 2 + nn], AH0, bh[2 * nn], bh[2 * nn + 1]);
                            MMAU4(acc[1][p * 2 + nn], AH1, bh[2 * nn], bh[2 * nn + 1]);
                            MMAU4(acc[0][p * 2 + nn], AH0, bl[2 * nn], bl[2 * nn + 1]);
                            MMAU4(acc[1][p * 2 + nn], AH1, bl[2 * nn], bl[2 * nn + 1]);
                            MMAU4(acc[0][p * 2 + nn], AL0, bh[2 * nn], bh[2 * nn + 1]);
                            MMAU4(acc[1][p * 2 + nn], AL1, bh[2 * nn], bh[2 * nn + 1]);
                        }
                    }
                }
            }

            if (ic < 3) {
                CP_WAIT0();        // X(ic+1) landed (was hidden by compute)
                __syncthreads();   // all warps done reading Xb; swap safe
            }
        }
    }

    // ---- epilogue: add bias, store float2 ----
    const int g = lane >> 2, tg = lane & 3;
#pragma unroll
    for (int mi = 0; mi < 2; ++mi) {
        int o1 = o0 + wm * 32 + mi * 16 + g;
        float bv1 = bias[o1], bv2 = bias[o1 + 8];
        float* r1 = out + ((size_t)(b * O_ + o1)) * T_ + t0 + wn * 64 + tg * 2;
        float* r2 = r1 + 8 * T_;
#pragma unroll
        for (int nf = 0; nf < 8; ++nf) {
            float2 v1 = make_float2(acc[mi][nf][0] + bv1, acc[mi][nf][1] + bv1);
            float2 v2 = make_float2(acc[mi][nf][2] + bv2, acc[mi][nf][3] + bv2);
            *(float2*)(r1 + nf * 8) = v1;
            *(float2*)(r2 + nf * 8) = v2;
        }
    }
}

// ---------------------------------------------------------------------------
// Launch (2 kernels)
// ---------------------------------------------------------------------------
extern "C" void kernel_launch(void* const* d_in, const int* in_sizes, int n_in,
                              void* d_out, int out_size) {
    const float* x      = (const float*)d_in[0];
    const float* weight = (const float*)d_in[1];
    const float* P      = (const float*)d_in[2];
    const float* bias   = (const float*)d_in[3];
    float* out          = (float*)d_out;

    prep<<<4096 + 256, 256>>>(x, weight, P);

    cudaFuncSetAttribute(conv_mma, cudaFuncAttributeMaxDynamicSharedMemorySize, DSMEM);
    conv_mma<<<dim3(64, 2), 512, DSMEM>>>(bias, out);
}

// round 13
// speedup vs baseline: 1.3380x; 1.3380x over previous
#include <cuda_runtime.h>
#include <cuda_fp16.h>
#include <cstdint>

// ---------------------------------------------------------------------------
// Dcls1d via mma.sync (HMMA) fp16 GEMM, ACTIVE-d COMPACTION.
//   out[b,o,t] = bias[o] + sum_{d,i} K2[d,o,i] * x[b,i,t+d-16]
//   X stored exactly as fp16 hi+lo; K2 as single fp16 (error ~1.6e-4 rms).
//   Products: Kh*Xh + Kh*Xl = Kh*X, fp32 accum. 2 MMAs per fragment.
// R13: R11 skeleton (group-local A sync via named barriers, ic-chunk 64),
//      fp16 2-product math. 2 launches.
// ---------------------------------------------------------------------------

#define B_   8
#define C_   256
#define T_   2048
#define O_   256
#define DKS_ 33
#define KC_  16
#define TP_  2080   // 16 + 2048 + 16 padded time rows

__device__ __align__(16) __half g_Kh[DKS_ * O_ * C_];   // [d][o][i], fp16
__device__ __align__(16) __half g_Xhi[B_ * TP_ * C_];   // [b][t+16][i]
__device__ __align__(16) __half g_Xlo[B_ * TP_ * C_];
__device__ unsigned long long g_maskblk[O_];            // per-o nonzero mask

// ---- PTX helpers -----------------------------------------------------------
__device__ __forceinline__ uint32_t smem_u32(const void* p) {
    uint32_t a;
    asm("{ .reg .u64 t; cvta.to.shared.u64 t, %1; cvt.u32.u64 %0, t; }"
        : "=r"(a) : "l"(p));
    return a;
}
__device__ __forceinline__ void cpa16(uint32_t dst, const void* src) {
    asm volatile("cp.async.ca.shared.global [%0], [%1], 16;" :: "r"(dst), "l"(src));
}
#define CP_COMMIT() asm volatile("cp.async.commit_group;" ::: "memory")
#define CP_WAIT0()  asm volatile("cp.async.wait_group 0;" ::: "memory")
#define GROUP_BAR(id) asm volatile("bar.sync %0, 128;" :: "r"(id) : "memory")

__device__ __forceinline__ void ldmx4(uint32_t* r, uint32_t addr) {
    asm volatile("ldmatrix.sync.aligned.m8n8.x4.shared.b16 {%0,%1,%2,%3}, [%4];"
                 : "=r"(r[0]), "=r"(r[1]), "=r"(r[2]), "=r"(r[3]) : "r"(addr));
}
#define MMA(dv, a, b0v, b1v)                                                   \
    asm volatile("mma.sync.aligned.m16n8k16.row.col.f32.f16.f16.f32 "          \
                 "{%0,%1,%2,%3},{%4,%5,%6,%7},{%8,%9},{%0,%1,%2,%3};"          \
                 : "+f"((dv)[0]), "+f"((dv)[1]), "+f"((dv)[2]), "+f"((dv)[3])  \
                 : "r"((a)[0]), "r"((a)[1]), "r"((a)[2]), "r"((a)[3]),         \
                   "r"(b0v), "r"(b1v))

// ---------------------------------------------------------------------------
// Fused prep: blocks [0,4096) x transpose/split+pads; [4096,4352) build K2.
// ---------------------------------------------------------------------------
__global__ void prep(const float* __restrict__ x,
                     const float* __restrict__ w,
                     const float* __restrict__ P) {
    __shared__ float sm[32][33];
    __shared__ unsigned long long s_m[8];
    const int tid = threadIdx.x;

    if (blockIdx.x < 4096) {
        int blk = blockIdx.x;
        int t0 = (blk & 63) * 32;
        int i0 = ((blk >> 6) & 7) * 32;
        int b  = blk >> 9;
        int tl = tid & 31, th = tid >> 5;

        if ((blk & 63) == 0) {   // zero pads
#pragma unroll
            for (int k = 0; k < 2; ++k) {
                int e = tid + k * 256;
                int r = e >> 5, cc = e & 31;
                size_t o1 = ((size_t)b * TP_ + r) * C_ + i0 + cc;
                size_t o2 = ((size_t)b * TP_ + (TP_ - 16 + r)) * C_ + i0 + cc;
                g_Xhi[o1] = __float2half(0.f);
                g_Xlo[o1] = __float2half(0.f);
                g_Xhi[o2] = __float2half(0.f);
                g_Xlo[o2] = __float2half(0.f);
            }
        }
#pragma unroll
        for (int k = 0; k < 4; ++k) {
            int i = i0 + th + k * 8;
            sm[th + k * 8][tl] = x[((size_t)b * C_ + i) * T_ + t0 + tl];
        }
        __syncthreads();
#pragma unroll
        for (int k = 0; k < 4; ++k) {
            int t = t0 + th + k * 8;
            float v = sm[tl][th + k * 8];
            __half h = __float2half(v);
            __half l = __float2half(v - __half2float(h));
            size_t idx = ((size_t)b * TP_ + t + 16) * C_ + i0 + tl;
            g_Xhi[idx] = h;
            g_Xlo[idx] = l;
        }
    } else {
        // ---- build_k2 (gather form, no local memory) ----
        int bk = blockIdx.x - 4096;               // out-channel o
        int oi = bk * 256 + tid;                  // tid = input channel i
        const float* Prow  = P + (size_t)oi * KC_;
        const float* P0row = P + (size_t)tid * KC_;  // out-channel 0 (frac src)
        const float* Wrow  = w + (size_t)oi * KC_;

        int   pi[KC_];
        float c1[KC_], c2[KC_];
#pragma unroll
        for (int k = 0; k < KC_; ++k) {
            float pp  = Prow[k] + 16.f;
            pi[k]     = (int)floorf(pp);
            float pp0 = P0row[k] + 16.f;
            float fr  = pp0 - floorf(pp0);
            float wv  = Wrow[k];
            c1[k] = wv * (1.f - fr);
            c2[k] = wv * fr;
        }
        unsigned long long bits = 0ull;
#pragma unroll
        for (int d = 0; d < DKS_; ++d) {
            float v = 0.f;
#pragma unroll
            for (int k = 0; k < KC_; ++k) {
                if (pi[k] == d)     v += c1[k];
                if (pi[k] + 1 == d) v += c2[k];
            }
            if (v != 0.f) bits |= 1ull << d;
            g_Kh[(size_t)(d * O_ + bk) * C_ + tid] = __float2half(v);
        }
#pragma unroll
        for (int s = 16; s > 0; s >>= 1)
            bits |= __shfl_xor_sync(0xffffffffu, bits, s);
        if ((tid & 31) == 0) s_m[tid >> 5] = bits;
        __syncthreads();
        if (tid == 0) {
            unsigned long long m = 0ull;
#pragma unroll
            for (int q = 0; q < 8; ++q) m |= s_m[q];
            g_maskblk[bk] = m;
        }
    }
}

// ---------------------------------------------------------------------------
// GEMM kernel.
// Block: 128 o x 256 t, 512 threads (16 warps: 4Mx4N, warp = 32 o x 64 t).
// ic-chunk = 64 i (4 chunks). smem rows 144B (conflict-free LDSM).
//   A (K2[d]): 128 x 64 i fp16 (single tensor), double buffered; each
//     wm-group stages/syncs only its own 32 rows (named barrier wm+1).
//   X: 288 x 64 i, hi+lo (per-ic, block barrier).
// ---------------------------------------------------------------------------
#define ROWB   144u
#define A_TS   18432u      // one A tensor (128*144)
#define X_OFF  36864u      // 2 A buffers
#define X_TS   41472u      // one X tensor (288*144)
#define DSMEM  (36864u + 2u * 41472u + 128u)   // ~117 KB

__device__ __forceinline__ void stage_A_grp(uint32_t A0, int d, int slot,
                                            int o0, int ic, int wm, int gt) {
    uint32_t Ab = A0 + (uint32_t)slot * A_TS;
#pragma unroll
    for (int k = 0; k < 2; ++k) {
        int idx = gt + k * 128;                  // 256 chunks (32r x 8c)
        int r   = (idx >> 3) & 31;
        int c   = idx & 7;
        int row = wm * 32 + r;
        const __half* src = g_Kh
            + ((size_t)(d * 256 + o0 + row) * 256 + ic * 64 + c * 8);
        cpa16(Ab + row * ROWB + c * 16, src);
    }
}

__global__ __launch_bounds__(512, 1)
void conv_mma(const float* __restrict__ bias, float* __restrict__ out) {
    extern __shared__ char dsm_raw[];
    uint32_t raw  = smem_u32(dsm_raw);
    uint32_t base = (raw + 127u) & ~127u;

    __shared__ unsigned long long s_part[4];
    __shared__ int s_act[DKS_];
    __shared__ int s_n;

    const int tid  = threadIdx.x;
    const int lane = tid & 31, w = tid >> 5;
    const int wm = w & 3, wn = w >> 2;            // 4 M-warps x 4 N-warps
    const int gt = wn * 32 + lane;                // index within wm-group
    const int b  = blockIdx.x >> 3;
    const int t0 = (blockIdx.x & 7) * 256;
    const int o0 = blockIdx.y * 128;

    // ---- prologue: OR-reduce per-o masks -> active-d list ----
    if (tid < 128) {
        unsigned long long m = g_maskblk[o0 + tid];
#pragma unroll
        for (int s = 16; s > 0; s >>= 1)
            m |= __shfl_xor_sync(0xffffffffu, m, s);
        if (lane == 0) s_part[w] = m;
    }
    __syncthreads();
    if (tid == 0) {
        unsigned long long m = s_part[0] | s_part[1] | s_part[2] | s_part[3];
        int n = 0;
        for (int d = 0; d < DKS_; ++d)
            if (m & (1ull << d)) s_act[n++] = d;
        s_n = n;
    }
    __syncthreads();
    const int n_act = s_n;

    const uint32_t A0 = base;
    const uint32_t X0 = base + X_OFF;

    float acc[2][8][4];
#pragma unroll
    for (int mi = 0; mi < 2; ++mi)
#pragma unroll
        for (int nf = 0; nf < 8; ++nf)
#pragma unroll
            for (int q = 0; q < 4; ++q) acc[mi][nf][q] = 0.f;

    // ldmatrix per-lane row/col offsets
    const uint32_t a_r = (lane & 7) + 8 * ((lane >> 3) & 1);
    const uint32_t a_c = (uint32_t)(lane >> 4) * 16;
    const uint32_t b_r = (lane & 7) + 8 * (lane >> 4);
    const uint32_t b_c = (uint32_t)((lane >> 3) & 1) * 16;

    for (int ic = 0; ic < 4 && n_act > 0; ++ic) {
        __syncthreads();    // all groups done with X (and A bufs) of prev ic
        // ---- stage X tile (288 rows x 64 i, hi+lo): 4608 chunks ----
#pragma unroll
        for (int k = 0; k < 9; ++k) {
            int idx = tid + k * 512;
            int tn  = idx >= 2304;
            int r   = (idx - tn * 2304) >> 3;
            int c   = idx & 7;
            const __half* src = (tn ? g_Xlo : g_Xhi)
                + ((size_t)(b * TP_ + t0 + r) * 256 + ic * 64 + c * 8);
            cpa16(X0 + (uint32_t)tn * X_TS + r * ROWB + c * 16, src);
        }
        // ---- stage A(act[0]) group rows into buf0 ----
        stage_A_grp(A0, s_act[0], 0, o0, ic, wm, gt);
        CP_COMMIT();

#pragma unroll 1
        for (int j = 0; j < n_act; ++j) {
            const int d = s_act[j];
            CP_WAIT0();            // own X+A(j) chunks landed
            if (j == 0) __syncthreads();   // X visible to all
            else        GROUP_BAR(wm + 1); // A(j) visible in group;
                                           // group done reading slot (j+1)&1

            if (j < n_act - 1) {   // overlap A(j+1) group-copy with compute(j)
                stage_A_grp(A0, s_act[j + 1], (j + 1) & 1, o0, ic, wm, gt);
                CP_COMMIT();
            }

            const uint32_t Ab = A0 + (uint32_t)(j & 1) * A_TS;
#pragma unroll
            for (int kk = 0; kk < 4; ++kk) {
                uint32_t ah[2][4];
#pragma unroll
                for (int mi = 0; mi < 2; ++mi) {
                    uint32_t ad = Ab + (wm * 32 + mi * 16 + a_r) * ROWB
                                + kk * 32 + a_c;
                    ldmx4(ah[mi], ad);
                }
#pragma unroll
                for (int p = 0; p < 4; ++p) {
                    uint32_t bh[4], bl[4];
                    uint32_t bd = X0 + (wn * 64 + d + p * 16 + b_r) * ROWB
                                + kk * 32 + b_c;
                    ldmx4(bh, bd);
                    ldmx4(bl, bd + X_TS);
#pragma unroll
                    for (int mi = 0; mi < 2; ++mi)
#pragma unroll
                        for (int nn = 0; nn < 2; ++nn) {
                            MMA(acc[mi][p * 2 + nn], ah[mi], bh[2 * nn], bh[2 * nn + 1]);
                            MMA(acc[mi][p * 2 + nn], ah[mi], bl[2 * nn], bl[2 * nn + 1]);
                        }
                }
            }
        }
    }

    // ---- epilogue: add bias, store float2 ----
    const int g = lane >> 2, tg = lane & 3;
#pragma unroll
    for (int mi = 0; mi < 2; ++mi) {
        int o1 = o0 + wm * 32 + mi * 16 + g;
        float bv1 = bias[o1], bv2 = bias[o1 + 8];
        float* r1 = out + ((size_t)(b * O_ + o1)) * T_ + t0 + wn * 64 + tg * 2;
        float* r2 = r1 + 8 * T_;
#pragma unroll
        for (int nf = 0; nf < 8; ++nf) {
            float2 v1 = make_float2(acc[mi][nf][0] + bv1, acc[mi][nf][1] + bv1);
            float2 v2 = make_float2(acc[mi][nf][2] + bv2, acc[mi][nf][3] + bv2);
            *(float2*)(r1 + nf * 8) = v1;
            *(float2*)(r2 + nf * 8) = v2;
        }
    }
}

// ---------------------------------------------------------------------------
// Launch (2 kernels)
// ---------------------------------------------------------------------------
extern "C" void kernel_launch(void* const* d_in, const int* in_sizes, int n_in,
                              void* d_out, int out_size) {
    const float* x      = (const float*)d_in[0];
    const float* weight = (const float*)d_in[1];
    const float* P      = (const float*)d_in[2];
    const float* bias   = (const float*)d_in[3];
    float* out          = (float*)d_out;

    prep<<<4096 + 256, 256>>>(x, weight, P);

    cudaFuncSetAttribute(conv_mma, cudaFuncAttributeMaxDynamicSharedMemorySize, DSMEM);
    conv_mma<<<dim3(64, 2), 512, DSMEM>>>(bias, out);
}

// round 14
// speedup vs baseline: 1.9072x; 1.4253x over previous
#include <cuda_runtime.h>
#include <cuda_fp16.h>
#include <cstdint>

// ---------------------------------------------------------------------------
// Dcls1d via mma.sync (HMMA) fp16 GEMM, ACTIVE-d COMPACTION.
//   out[b,o,t] = bias[o] + sum_{d,i} K2[d,o,i] * x[b,i,t+d-16]
//   K2 and X both single fp16 (validated error model: ~2.9e-4 rel l2,
//   3.4x under the 1e-3 threshold). ONE MMA per fragment, fp32 accum.
// R14: R13 skeleton (group-local A sync, ic-chunk 64); X-lo dropped.
// ---------------------------------------------------------------------------

#define B_   8
#define C_   256
#define T_   2048
#define O_   256
#define DKS_ 33
#define KC_  16
#define TP_  2080   // 16 + 2048 + 16 padded time rows

__device__ __align__(16) __half g_Kh[DKS_ * O_ * C_];   // [d][o][i], fp16
__device__ __align__(16) __half g_Xh[B_ * TP_ * C_];    // [b][t+16][i], fp16
__device__ unsigned long long g_maskblk[O_];            // per-o nonzero mask

// ---- PTX helpers -----------------------------------------------------------
__device__ __forceinline__ uint32_t smem_u32(const void* p) {
    uint32_t a;
    asm("{ .reg .u64 t; cvta.to.shared.u64 t, %1; cvt.u32.u64 %0, t; }"
        : "=r"(a) : "l"(p));
    return a;
}
__device__ __forceinline__ void cpa16(uint32_t dst, const void* src) {
    asm volatile("cp.async.ca.shared.global [%0], [%1], 16;" :: "r"(dst), "l"(src));
}
#define CP_COMMIT() asm volatile("cp.async.commit_group;" ::: "memory")
#define CP_WAIT0()  asm volatile("cp.async.wait_group 0;" ::: "memory")
#define GROUP_BAR(id) asm volatile("bar.sync %0, 128;" :: "r"(id) : "memory")

__device__ __forceinline__ void ldmx4(uint32_t* r, uint32_t addr) {
    asm volatile("ldmatrix.sync.aligned.m8n8.x4.shared.b16 {%0,%1,%2,%3}, [%4];"
                 : "=r"(r[0]), "=r"(r[1]), "=r"(r[2]), "=r"(r[3]) : "r"(addr));
}
#define MMA(dv, a, b0v, b1v)                                                   \
    asm volatile("mma.sync.aligned.m16n8k16.row.col.f32.f16.f16.f32 "          \
                 "{%0,%1,%2,%3},{%4,%5,%6,%7},{%8,%9},{%0,%1,%2,%3};"          \
                 : "+f"((dv)[0]), "+f"((dv)[1]), "+f"((dv)[2]), "+f"((dv)[3])  \
                 : "r"((a)[0]), "r"((a)[1]), "r"((a)[2]), "r"((a)[3]),         \
                   "r"(b0v), "r"(b1v))

// ---------------------------------------------------------------------------
// Fused prep: blocks [0,4096) x transpose+fp16; [4096,4352) build K2.
// ---------------------------------------------------------------------------
__global__ void prep(const float* __restrict__ x,
                     const float* __restrict__ w,
                     const float* __restrict__ P) {
    __shared__ float sm[32][33];
    __shared__ unsigned long long s_m[8];
    const int tid = threadIdx.x;

    if (blockIdx.x < 4096) {
        int blk = blockIdx.x;
        int t0 = (blk & 63) * 32;
        int i0 = ((blk >> 6) & 7) * 32;
        int b  = blk >> 9;
        int tl = tid & 31, th = tid >> 5;

        if ((blk & 63) == 0) {   // zero pads
#pragma unroll
            for (int k = 0; k < 2; ++k) {
                int e = tid + k * 256;
                int r = e >> 5, cc = e & 31;
                g_Xh[((size_t)b * TP_ + r) * C_ + i0 + cc] = __float2half(0.f);
                g_Xh[((size_t)b * TP_ + (TP_ - 16 + r)) * C_ + i0 + cc] = __float2half(0.f);
            }
        }
#pragma unroll
        for (int k = 0; k < 4; ++k) {
            int i = i0 + th + k * 8;
            sm[th + k * 8][tl] = x[((size_t)b * C_ + i) * T_ + t0 + tl];
        }
        __syncthreads();
#pragma unroll
        for (int k = 0; k < 4; ++k) {
            int t = t0 + th + k * 8;
            g_Xh[((size_t)b * TP_ + t + 16) * C_ + i0 + tl] =
                __float2half(sm[tl][th + k * 8]);
        }
    } else {
        // ---- build_k2 (gather form, no local memory) ----
        int bk = blockIdx.x - 4096;               // out-channel o
        int oi = bk * 256 + tid;                  // tid = input channel i
        const float* Prow  = P + (size_t)oi * KC_;
        const float* P0row = P + (size_t)tid * KC_;  // out-channel 0 (frac src)
        const float* Wrow  = w + (size_t)oi * KC_;

        int   pi[KC_];
        float c1[KC_], c2[KC_];
#pragma unroll
        for (int k = 0; k < KC_; ++k) {
            float pp  = Prow[k] + 16.f;
            pi[k]     = (int)floorf(pp);
            float pp0 = P0row[k] + 16.f;
            float fr  = pp0 - floorf(pp0);
            float wv  = Wrow[k];
            c1[k] = wv * (1.f - fr);
            c2[k] = wv * fr;
        }
        unsigned long long bits = 0ull;
#pragma unroll
        for (int d = 0; d < DKS_; ++d) {
            float v = 0.f;
#pragma unroll
            for (int k = 0; k < KC_; ++k) {
                if (pi[k] == d)     v += c1[k];
                if (pi[k] + 1 == d) v += c2[k];
            }
            if (v != 0.f) bits |= 1ull << d;
            g_Kh[(size_t)(d * O_ + bk) * C_ + tid] = __float2half(v);
        }
#pragma unroll
        for (int s = 16; s > 0; s >>= 1)
            bits |= __shfl_xor_sync(0xffffffffu, bits, s);
        if ((tid & 31) == 0) s_m[tid >> 5] = bits;
        __syncthreads();
        if (tid == 0) {
            unsigned long long m = 0ull;
#pragma unroll
            for (int q = 0; q < 8; ++q) m |= s_m[q];
            g_maskblk[bk] = m;
        }
    }
}

// ---------------------------------------------------------------------------
// GEMM kernel.
// Block: 128 o x 256 t, 512 threads (16 warps: 4Mx4N, warp = 32 o x 64 t).
// ic-chunk = 64 i (4 chunks). smem rows 144B (conflict-free LDSM).
//   A (K2[d]): 128 x 64 i fp16, double buffered; wm-group stages/syncs only
//     its own 32 rows (named barrier wm+1).
//   X: 288 x 64 i fp16 (per-ic, block barrier).
// ---------------------------------------------------------------------------
#define ROWB   144u
#define A_TS   18432u      // one A tensor (128*144)
#define X_OFF  36864u      // after 2 A buffers
#define X_TS   41472u      // X tensor (288*144)
#define DSMEM  (36864u + 41472u + 128u)   // ~78 KB

__device__ __forceinline__ void stage_A_grp(uint32_t A0, int d, int slot,
                                            int o0, int ic, int wm, int gt) {
    uint32_t Ab = A0 + (uint32_t)slot * A_TS;
#pragma unroll
    for (int k = 0; k < 2; ++k) {
        int idx = gt + k * 128;                  // 256 chunks (32r x 8c)
        int r   = (idx >> 3) & 31;
        int c   = idx & 7;
        int row = wm * 32 + r;
        const __half* src = g_Kh
            + ((size_t)(d * 256 + o0 + row) * 256 + ic * 64 + c * 8);
        cpa16(Ab + row * ROWB + c * 16, src);
    }
}

__global__ __launch_bounds__(512, 1)
void conv_mma(const float* __restrict__ bias, float* __restrict__ out) {
    extern __shared__ char dsm_raw[];
    uint32_t raw  = smem_u32(dsm_raw);
    uint32_t base = (raw + 127u) & ~127u;

    __shared__ unsigned long long s_part[4];
    __shared__ int s_act[DKS_];
    __shared__ int s_n;

    const int tid  = threadIdx.x;
    const int lane = tid & 31, w = tid >> 5;
    const int wm = w & 3, wn = w >> 2;            // 4 M-warps x 4 N-warps
    const int gt = wn * 32 + lane;                // index within wm-group
    const int b  = blockIdx.x >> 3;
    const int t0 = (blockIdx.x & 7) * 256;
    const int o0 = blockIdx.y * 128;

    // ---- prologue: OR-reduce per-o masks -> active-d list ----
    if (tid < 128) {
        unsigned long long m = g_maskblk[o0 + tid];
#pragma unroll
        for (int s = 16; s > 0; s >>= 1)
            m |= __shfl_xor_sync(0xffffffffu, m, s);
        if (lane == 0) s_part[w] = m;
    }
    __syncthreads();
    if (tid == 0) {
        unsigned long long m = s_part[0] | s_part[1] | s_part[2] | s_part[3];
        int n = 0;
        for (int d = 0; d < DKS_; ++d)
            if (m & (1ull << d)) s_act[n++] = d;
        s_n = n;
    }
    __syncthreads();
    const int n_act = s_n;

    const uint32_t A0 = base;
    const uint32_t X0 = base + X_OFF;

    float acc[2][8][4];
#pragma unroll
    for (int mi = 0; mi < 2; ++mi)
#pragma unroll
        for (int nf = 0; nf < 8; ++nf)
#pragma unroll
            for (int q = 0; q < 4; ++q) acc[mi][nf][q] = 0.f;

    // ldmatrix per-lane row/col offsets
    const uint32_t a_r = (lane & 7) + 8 * ((lane >> 3) & 1);
    const uint32_t a_c = (uint32_t)(lane >> 4) * 16;
    const uint32_t b_r = (lane & 7) + 8 * (lane >> 4);
    const uint32_t b_c = (uint32_t)((lane >> 3) & 1) * 16;

    for (int ic = 0; ic < 4 && n_act > 0; ++ic) {
        __syncthreads();    // all groups done with X (and A bufs) of prev ic
        // ---- stage X tile (288 rows x 64 i): 2304 x 16B chunks ----
#pragma unroll
        for (int k = 0; k < 5; ++k) {
            int idx = tid + k * 512;
            if (idx < 2304) {
                int r = idx >> 3;
                int c = idx & 7;
                const __half* src = g_Xh
                    + ((size_t)(b * TP_ + t0 + r) * 256 + ic * 64 + c * 8);
                cpa16(X0 + r * ROWB + c * 16, src);
            }
        }
        // ---- stage A(act[0]) group rows into buf0 ----
        stage_A_grp(A0, s_act[0], 0, o0, ic, wm, gt);
        CP_COMMIT();

#pragma unroll 1
        for (int j = 0; j < n_act; ++j) {
            const int d = s_act[j];
            CP_WAIT0();            // own X+A(j) chunks landed
            if (j == 0) __syncthreads();   // X visible to all
            else        GROUP_BAR(wm + 1); // A(j) visible in group;
                                           // group done reading slot (j+1)&1

            if (j < n_act - 1) {   // overlap A(j+1) group-copy with compute(j)
                stage_A_grp(A0, s_act[j + 1], (j + 1) & 1, o0, ic, wm, gt);
                CP_COMMIT();
            }

            const uint32_t Ab = A0 + (uint32_t)(j & 1) * A_TS;
#pragma unroll
            for (int kk = 0; kk < 4; ++kk) {
                uint32_t ah[2][4];
#pragma unroll
                for (int mi = 0; mi < 2; ++mi) {
                    uint32_t ad = Ab + (wm * 32 + mi * 16 + a_r) * ROWB
                                + kk * 32 + a_c;
                    ldmx4(ah[mi], ad);
                }
#pragma unroll
                for (int p = 0; p < 4; ++p) {
                    uint32_t bh[4];
                    uint32_t bd = X0 + (wn * 64 + d + p * 16 + b_r) * ROWB
                                + kk * 32 + b_c;
                    ldmx4(bh, bd);
#pragma unroll
                    for (int mi = 0; mi < 2; ++mi)
#pragma unroll
                        for (int nn = 0; nn < 2; ++nn)
                            MMA(acc[mi][p * 2 + nn], ah[mi], bh[2 * nn], bh[2 * nn + 1]);
                }
            }
        }
    }

    // ---- epilogue: add bias, store float2 ----
    const int g = lane >> 2, tg = lane & 3;
#pragma unroll
    for (int mi = 0; mi < 2; ++mi) {
        int o1 = o0 + wm * 32 + mi * 16 + g;
        float bv1 = bias[o1], bv2 = bias[o1 + 8];
        float* r1 = out + ((size_t)(b * O_ + o1)) * T_ + t0 + wn * 64 + tg * 2;
        float* r2 = r1 + 8 * T_;
#pragma unroll
        for (int nf = 0; nf < 8; ++nf) {
            float2 v1 = make_float2(acc[mi][nf][0] + bv1, acc[mi][nf][1] + bv1);
            float2 v2 = make_float2(acc[mi][nf][2] + bv2, acc[mi][nf][3] + bv2);
            *(float2*)(r1 + nf * 8) = v1;
            *(float2*)(r2 + nf * 8) = v2;
        }
    }
}

// ---------------------------------------------------------------------------
// Launch (2 kernels)
// ---------------------------------------------------------------------------
extern "C" void kernel_launch(void* const* d_in, const int* in_sizes, int n_in,
                              void* d_out, int out_size) {
    const float* x      = (const float*)d_in[0];
    const float* weight = (const float*)d_in[1];
    const float* P      = (const float*)d_in[2];
    const float* bias   = (const float*)d_in[3];
    float* out          = (float*)d_out;

    prep<<<4096 + 256, 256>>>(x, weight, P);

    cudaFuncSetAttribute(conv_mma, cudaFuncAttributeMaxDynamicSharedMemorySize, DSMEM);
    conv_mma<<<dim3(64, 2), 512, DSMEM>>>(bias, out);
}

// round 15
// speedup vs baseline: 1.9664x; 1.0310x over previous
#include <cuda_runtime.h>
#include <cuda_fp16.h>
#include <cstdint>

// ---------------------------------------------------------------------------
// Dcls1d via mma.sync (HMMA) fp16 GEMM, ACTIVE-d COMPACTION.
//   out[b,o,t] = bias[o] + sum_{d,i} K2[d,o,i] * x[b,i,t+d-16]
//   K2 and X single fp16 (validated error ~2.9e-4 rel l2). fp32 accum.
// R15: 3-slot A pipeline with cp.async.wait_group<=1 (no full drains),
//      ic-chunk 128 (2 chunks -> 14 sync points). Group-local A sync.
// ---------------------------------------------------------------------------

#define B_   8
#define C_   256
#define T_   2048
#define O_   256
#define DKS_ 33
#define KC_  16
#define TP_  2080   // 16 + 2048 + 16 padded time rows

__device__ __align__(16) __half g_Kh[DKS_ * O_ * C_];   // [d][o][i], fp16
__device__ __align__(16) __half g_Xh[B_ * TP_ * C_];    // [b][t+16][i], fp16
__device__ unsigned long long g_maskblk[O_];            // per-o nonzero mask

// ---- PTX helpers -----------------------------------------------------------
__device__ __forceinline__ uint32_t smem_u32(const void* p) {
    uint32_t a;
    asm("{ .reg .u64 t; cvta.to.shared.u64 t, %1; cvt.u32.u64 %0, t; }"
        : "=r"(a) : "l"(p));
    return a;
}
__device__ __forceinline__ void cpa16(uint32_t dst, const void* src) {
    asm volatile("cp.async.ca.shared.global [%0], [%1], 16;" :: "r"(dst), "l"(src));
}
#define CP_COMMIT() asm volatile("cp.async.commit_group;" ::: "memory")
#define CP_WAIT0()  asm volatile("cp.async.wait_group 0;" ::: "memory")
#define CP_WAIT1()  asm volatile("cp.async.wait_group 1;" ::: "memory")
#define GROUP_BAR(id) asm volatile("bar.sync %0, 128;" :: "r"(id) : "memory")

__device__ __forceinline__ void ldmx4(uint32_t* r, uint32_t addr) {
    asm volatile("ldmatrix.sync.aligned.m8n8.x4.shared.b16 {%0,%1,%2,%3}, [%4];"
                 : "=r"(r[0]), "=r"(r[1]), "=r"(r[2]), "=r"(r[3]) : "r"(addr));
}
#define MMA(dv, a, b0v, b1v)                                                   \
    asm volatile("mma.sync.aligned.m16n8k16.row.col.f32.f16.f16.f32 "          \
                 "{%0,%1,%2,%3},{%4,%5,%6,%7},{%8,%9},{%0,%1,%2,%3};"          \
                 : "+f"((dv)[0]), "+f"((dv)[1]), "+f"((dv)[2]), "+f"((dv)[3])  \
                 : "r"((a)[0]), "r"((a)[1]), "r"((a)[2]), "r"((a)[3]),         \
                   "r"(b0v), "r"(b1v))

// ---------------------------------------------------------------------------
// Fused prep: blocks [0,4096) x transpose+fp16; [4096,4352) build K2.
// ---------------------------------------------------------------------------
__global__ void prep(const float* __restrict__ x,
                     const float* __restrict__ w,
                     const float* __restrict__ P) {
    __shared__ float sm[32][33];
    __shared__ unsigned long long s_m[8];
    const int tid = threadIdx.x;

    if (blockIdx.x < 4096) {
        int blk = blockIdx.x;
        int t0 = (blk & 63) * 32;
        int i0 = ((blk >> 6) & 7) * 32;
        int b  = blk >> 9;
        int tl = tid & 31, th = tid >> 5;

        if ((blk & 63) == 0) {   // zero pads
#pragma unroll
            for (int k = 0; k < 2; ++k) {
                int e = tid + k * 256;
                int r = e >> 5, cc = e & 31;
                g_Xh[((size_t)b * TP_ + r) * C_ + i0 + cc] = __float2half(0.f);
                g_Xh[((size_t)b * TP_ + (TP_ - 16 + r)) * C_ + i0 + cc] = __float2half(0.f);
            }
        }
#pragma unroll
        for (int k = 0; k < 4; ++k) {
            int i = i0 + th + k * 8;
            sm[th + k * 8][tl] = x[((size_t)b * C_ + i) * T_ + t0 + tl];
        }
        __syncthreads();
#pragma unroll
        for (int k = 0; k < 4; ++k) {
            int t = t0 + th + k * 8;
            g_Xh[((size_t)b * TP_ + t + 16) * C_ + i0 + tl] =
                __float2half(sm[tl][th + k * 8]);
        }
    } else {
        // ---- build_k2 (gather form, no local memory) ----
        int bk = blockIdx.x - 4096;               // out-channel o
        int oi = bk * 256 + tid;                  // tid = input channel i
        const float* Prow  = P + (size_t)oi * KC_;
        const float* P0row = P + (size_t)tid * KC_;  // out-channel 0 (frac src)
        const float* Wrow  = w + (size_t)oi * KC_;

        int   pi[KC_];
        float c1[KC_], c2[KC_];
#pragma unroll
        for (int k = 0; k < KC_; ++k) {
            float pp  = Prow[k] + 16.f;
            pi[k]     = (int)floorf(pp);
            float pp0 = P0row[k] + 16.f;
            float fr  = pp0 - floorf(pp0);
            float wv  = Wrow[k];
            c1[k] = wv * (1.f - fr);
            c2[k] = wv * fr;
        }
        unsigned long long bits = 0ull;
#pragma unroll
        for (int d = 0; d < DKS_; ++d) {
            float v = 0.f;
#pragma unroll
            for (int k = 0; k < KC_; ++k) {
                if (pi[k] == d)     v += c1[k];
                if (pi[k] + 1 == d) v += c2[k];
            }
            if (v != 0.f) bits |= 1ull << d;
            g_Kh[(size_t)(d * O_ + bk) * C_ + tid] = __float2half(v);
        }
#pragma unroll
        for (int s = 16; s > 0; s >>= 1)
            bits |= __shfl_xor_sync(0xffffffffu, bits, s);
        if ((tid & 31) == 0) s_m[tid >> 5] = bits;
        __syncthreads();
        if (tid == 0) {
            unsigned long long m = 0ull;
#pragma unroll
            for (int q = 0; q < 8; ++q) m |= s_m[q];
            g_maskblk[bk] = m;
        }
    }
}

// ---------------------------------------------------------------------------
// GEMM kernel.
// Block: 128 o x 256 t, 512 threads (16 warps: 4Mx4N, warp = 32 o x 64 t).
// ic-chunk = 128 i (2 chunks). smem rows 272B (conflict-free LDSM).
//   A (K2[d]): 128 x 128 i fp16, 3 slots; wm-group stages/syncs its 32 rows.
//   X: 288 x 128 i fp16 (per-ic, block barrier).
// cp.async pipeline depth 2 (wait_group<=1): A(j+1) in flight during compute(j).
// ---------------------------------------------------------------------------
#define ROWB   272u
#define A_TS   34816u      // one A slot (128*272)
#define X_OFF  (3u * 34816u)        // 104448
#define X_TS   78336u      // X tensor (288*272)
#define DSMEM  (104448u + 78336u + 128u)   // ~183 KB

__device__ __forceinline__ void stage_A_grp(uint32_t A0, int d, int slot,
                                            int o0, int ic, int wm, int gt) {
    uint32_t Ab = A0 + (uint32_t)slot * A_TS;
#pragma unroll
    for (int k = 0; k < 4; ++k) {
        int idx = gt + k * 128;                  // 512 chunks (32r x 16c)
        int r   = (idx >> 4) & 31;
        int c   = idx & 15;
        int row = wm * 32 + r;
        const __half* src = g_Kh
            + ((size_t)(d * 256 + o0 + row) * 256 + ic * 128 + c * 8);
        cpa16(Ab + row * ROWB + c * 16, src);
    }
}

__global__ __launch_bounds__(512, 1)
void conv_mma(const float* __restrict__ bias, float* __restrict__ out) {
    extern __shared__ char dsm_raw[];
    uint32_t raw  = smem_u32(dsm_raw);
    uint32_t base = (raw + 127u) & ~127u;

    __shared__ unsigned long long s_part[4];
    __shared__ int s_act[DKS_];
    __shared__ int s_n;

    const int tid  = threadIdx.x;
    const int lane = tid & 31, w = tid >> 5;
    const int wm = w & 3, wn = w >> 2;            // 4 M-warps x 4 N-warps
    const int gt = wn * 32 + lane;                // index within wm-group
    const int b  = blockIdx.x >> 3;
    const int t0 = (blockIdx.x & 7) * 256;
    const int o0 = blockIdx.y * 128;

    // ---- prologue: OR-reduce per-o masks -> active-d list ----
    if (tid < 128) {
        unsigned long long m = g_maskblk[o0 + tid];
#pragma unroll
        for (int s = 16; s > 0; s >>= 1)
            m |= __shfl_xor_sync(0xffffffffu, m, s);
        if (lane == 0) s_part[w] = m;
    }
    __syncthreads();
    if (tid == 0) {
        unsigned long long m = s_part[0] | s_part[1] | s_part[2] | s_part[3];
        int n = 0;
        for (int d = 0; d < DKS_; ++d)
            if (m & (1ull << d)) s_act[n++] = d;
        s_n = n;
    }
    __syncthreads();
    const int n_act = s_n;

    const uint32_t A0 = base;
    const uint32_t X0 = base + X_OFF;

    float acc[2][8][4];
#pragma unroll
    for (int mi = 0; mi < 2; ++mi)
#pragma unroll
        for (int nf = 0; nf < 8; ++nf)
#pragma unroll
            for (int q = 0; q < 4; ++q) acc[mi][nf][q] = 0.f;

    // ldmatrix per-lane row/col offsets
    const uint32_t a_r = (lane & 7) + 8 * ((lane >> 3) & 1);
    const uint32_t a_c = (uint32_t)(lane >> 4) * 16;
    const uint32_t b_r = (lane & 7) + 8 * (lane >> 4);
    const uint32_t b_c = (uint32_t)((lane >> 3) & 1) * 16;

    for (int ic = 0; ic < 2 && n_act > 0; ++ic) {
        __syncthreads();    // all warps done with X (and A slots) of prev ic
        // ---- stage X tile (288 rows x 128 i): 4608 x 16B chunks ----
#pragma unroll
        for (int k = 0; k < 9; ++k) {
            int idx = tid + k * 512;
            int r = idx >> 4;
            int c = idx & 15;
            const __half* src = g_Xh
                + ((size_t)(b * TP_ + t0 + r) * 256 + ic * 128 + c * 8);
            cpa16(X0 + r * ROWB + c * 16, src);
        }
        // ---- stage A(act[0]) slot0 in same group as X ----
        stage_A_grp(A0, s_act[0], 0, o0, ic, wm, gt);
        CP_COMMIT();
        // ---- stage A(act[1]) slot1 (own group; may stay in flight) ----
        if (n_act > 1) stage_A_grp(A0, s_act[1], 1, o0, ic, wm, gt);
        CP_COMMIT();     // always commit (empty group ok) -> invariant holds

#pragma unroll 1
        for (int j = 0; j < n_act; ++j) {
            const int d = s_act[j];
            CP_WAIT1();            // all groups except the latest are done
                                   // => X (ic) and A(j) are complete
            if (j == 0) __syncthreads();   // X visible to all
            else        GROUP_BAR(wm + 1); // group finished compute(j-1):
                                           // slot (j+2)%3 == (j-1)%3 is free

            if (j + 2 < n_act)     // overlap A(j+2) copy with compute(j, j+1)
                stage_A_grp(A0, s_act[j + 2], (j + 2) % 3, o0, ic, wm, gt);
            CP_COMMIT();           // always commit (keeps wait_group semantics)

            const uint32_t Ab = A0 + (uint32_t)(j % 3) * A_TS;
#pragma unroll
            for (int kk = 0; kk < 8; ++kk) {
                uint32_t ah[2][4];
#pragma unroll
                for (int mi = 0; mi < 2; ++mi) {
                    uint32_t ad = Ab + (wm * 32 + mi * 16 + a_r) * ROWB
                                + kk * 32 + a_c;
                    ldmx4(ah[mi], ad);
                }
#pragma unroll
                for (int p = 0; p < 4; ++p) {
                    uint32_t bh[4];
                    uint32_t bd = X0 + (wn * 64 + d + p * 16 + b_r) * ROWB
                                + kk * 32 + b_c;
                    ldmx4(bh, bd);
#pragma unroll
                    for (int mi = 0; mi < 2; ++mi)
#pragma unroll
                        for (int nn = 0; nn < 2; ++nn)
                            MMA(acc[mi][p * 2 + nn], ah[mi], bh[2 * nn], bh[2 * nn + 1]);
                }
            }
        }
        CP_WAIT0();   // drain tail groups before X/A slots are reused next ic
    }

    // ---- epilogue: add bias, store float2 ----
    const int g = lane >> 2, tg = lane & 3;
#pragma unroll
    for (int mi = 0; mi < 2; ++mi) {
        int o1 = o0 + wm * 32 + mi * 16 + g;
        float bv1 = bias[o1], bv2 = bias[o1 + 8];
        float* r1 = out + ((size_t)(b * O_ + o1)) * T_ + t0 + wn * 64 + tg * 2;
        float* r2 = r1 + 8 * T_;
#pragma unroll
        for (int nf = 0; nf < 8; ++nf) {
            float2 v1 = make_float2(acc[mi][nf][0] + bv1, acc[mi][nf][1] + bv1);
            float2 v2 = make_float2(acc[mi][nf][2] + bv2, acc[mi][nf][3] + bv2);
            *(float2*)(r1 + nf * 8) = v1;
            *(float2*)(r2 + nf * 8) = v2;
        }
    }
}

// ---------------------------------------------------------------------------
// Launch (2 kernels)
// ---------------------------------------------------------------------------
extern "C" void kernel_launch(void* const* d_in, const int* in_sizes, int n_in,
                              void* d_out, int out_size) {
    const float* x      = (const float*)d_in[0];
    const float* weight = (const float*)d_in[1];
    const float* P      = (const float*)d_in[2];
    const float* bias   = (const float*)d_in[3];
    float* out          = (float*)d_out;

    prep<<<4096 + 256, 256>>>(x, weight, P);

    cudaFuncSetAttribute(conv_mma, cudaFuncAttributeMaxDynamicSharedMemorySize, DSMEM);
    conv_mma<<<dim3(64, 2), 512, DSMEM>>>(bias, out);
}